// round 1
// baseline (speedup 1.0000x reference)
#include <cuda_runtime.h>
#include <cstdint>

#define BB 4
#define TT 1024
#define DD 768
#define LL 4
#define DFF 3072
#define VV 50257

// ---------------- scratch (static __device__, no allocations) ----------------
__device__ float g_kwm[DD];
__device__ float g_kbm;
__device__ float g_kmean[BB * TT];
__device__ float g_w[BB * TT];
__device__ float g_xpart[64 * DD];          // 4 batches x 16 chunks
__device__ float g_x[BB * DD];              // layer state / xbar
__device__ float g_ctx[BB * DD];
__device__ float g_h[BB * DFF];
__device__ float g_part[16 * BB * DFF];     // split-K partials (max KC=16, N=3072)
__device__ float g_xn[BB * DD];             // ln_f output

__device__ __forceinline__ float warp_sum(float v) {
    #pragma unroll
    for (int o = 16; o; o >>= 1) v += __shfl_xor_sync(0xffffffffu, v, o);
    return v;
}

// ---------------- prep: kwm[i] = mean_d kw0[i,d]; kbm = mean(kb0) ------------
__global__ void k_prep(const float* __restrict__ kw0, const float* __restrict__ kb0) {
    if (blockIdx.x < 24) {
        int warp = threadIdx.x >> 5, lane = threadIdx.x & 31;
        int i = blockIdx.x * 8 + warp;
        const float* row = kw0 + (size_t)i * DD;
        float s = 0.f;
        for (int j = lane; j < DD; j += 32) s += row[j];
        s = warp_sum(s);
        if (lane == 0) g_kwm[i] = s * (1.0f / DD);
    } else {
        __shared__ float sh[256];
        float s = 0.f;
        for (int j = threadIdx.x; j < DD; j += 256) s += kb0[j];
        sh[threadIdx.x] = s; __syncthreads();
        for (int o = 128; o; o >>= 1) {
            if (threadIdx.x < o) sh[threadIdx.x] += sh[threadIdx.x + o];
            __syncthreads();
        }
        if (threadIdx.x == 0) g_kbm = sh[0] * (1.0f / DD);
    }
}

// ---------------- k_mean[b,t] = (wte[idx]+wpe[t]) . kwm + kbm ----------------
__global__ void k_kmean(const int* __restrict__ idx, const float* __restrict__ wte,
                        const float* __restrict__ wpe) {
    int warp = threadIdx.x >> 5, lane = threadIdx.x & 31;
    int tok = blockIdx.x * 8 + warp;          // 0..4095
    int t = tok & (TT - 1);
    int row = idx[tok];
    const float* e = wte + (size_t)row * DD;
    const float* p = wpe + (size_t)t * DD;
    float s = 0.f;
    for (int j = lane; j < DD; j += 32) s += (e[j] + p[j]) * g_kwm[j];
    s = warp_sum(s);
    if (lane == 0) g_kmean[tok] = s + g_kbm;
}

// ---------------- softmax over T of cos(k_mean), per batch -------------------
__global__ void k_softmax() {
    __shared__ float sh[TT];
    int b = blockIdx.x, t = threadIdx.x;
    float s = cosf(g_kmean[b * TT + t]);
    sh[t] = s; __syncthreads();
    for (int o = 512; o; o >>= 1) {
        if (t < o) sh[t] = fmaxf(sh[t], sh[t + o]);
        __syncthreads();
    }
    float mx = sh[0]; __syncthreads();
    float e = expf(s - mx);
    sh[t] = e; __syncthreads();
    for (int o = 512; o; o >>= 1) {
        if (t < o) sh[t] += sh[t + o];
        __syncthreads();
    }
    g_w[b * TT + t] = e / sh[0];
}

// ---------------- xbar partials: 64-token chunks -----------------------------
__global__ void k_xbar(const int* __restrict__ idx, const float* __restrict__ wte,
                       const float* __restrict__ wpe) {
    __shared__ float ww[64];
    __shared__ int rows[64];
    int b = blockIdx.x >> 4, c = blockIdx.x & 15;
    if (threadIdx.x < 64) {
        int t = c * 64 + threadIdx.x;
        ww[threadIdx.x] = g_w[b * TT + t];
        rows[threadIdx.x] = idx[b * TT + t];
    }
    __syncthreads();
    int d = threadIdx.x;   // 768 threads
    float acc = 0.f;
    #pragma unroll 4
    for (int j = 0; j < 64; j++) {
        int t = c * 64 + j;
        acc += ww[j] * (wte[(size_t)rows[j] * DD + d] + wpe[(size_t)t * DD + d]);
    }
    g_xpart[(size_t)blockIdx.x * DD + d] = acc;
}

__global__ void k_xbar_reduce() {
    int b = blockIdx.x, d = threadIdx.x;
    float s = 0.f;
    #pragma unroll
    for (int c = 0; c < 16; c++) s += g_xpart[(size_t)(b * 16 + c) * DD + d];
    g_x[b * DD + d] = s;
}

// ---------------- skinny GEMM, split-K partials (deterministic) --------------
// part[(kc*4+b)*N + n] = sum over this k-chunk of A[b,k]*W[k,n]
__global__ void k_gemm4(const float* __restrict__ A, const float* __restrict__ W,
                        int K, int N, int kc) {
    __shared__ float sA[BB][192];
    int k0 = blockIdx.y * kc;
    for (int i = threadIdx.x; i < BB * kc; i += 128) {
        int b = i / kc, kk = i % kc;
        sA[b][kk] = A[b * K + k0 + kk];
    }
    __syncthreads();
    int n = blockIdx.x * 128 + threadIdx.x;
    float a0 = 0.f, a1 = 0.f, a2 = 0.f, a3 = 0.f;
    const float* Wp = W + (size_t)k0 * N + n;
    #pragma unroll 8
    for (int kk = 0; kk < kc; kk++) {
        float w = Wp[(size_t)kk * N];
        a0 += sA[0][kk] * w;
        a1 += sA[1][kk] * w;
        a2 += sA[2][kk] * w;
        a3 += sA[3][kk] * w;
    }
    size_t base = (size_t)blockIdx.y * BB * N + n;
    g_part[base]         = a0;
    g_part[base + N]     = a1;
    g_part[base + 2 * N] = a2;
    g_part[base + 3 * N] = a3;
}

__global__ void k_finish(float* __restrict__ out, const float* __restrict__ bias,
                         int N, int KC, int act) {
    int n = blockIdx.x * 256 + threadIdx.x;
    if (n >= N) return;
    int b = blockIdx.y;
    float s = 0.f;
    for (int kc = 0; kc < KC; kc++) s += g_part[((size_t)kc * BB + b) * N + n];
    if (bias) s += bias[n];
    if (act) s = 0.5f * s * (1.0f + erff(s * 0.70710678118654752f));  // exact GELU
    out[b * N + n] = s;
}

// ---------------- ln_f on (B,D) state ----------------------------------------
__global__ void k_lnf(const float* __restrict__ lnw) {
    __shared__ float sh[256];
    int b = blockIdx.x;
    const float* x = g_x + b * DD;
    float s = 0.f;
    for (int j = threadIdx.x; j < DD; j += 256) s += x[j];
    sh[threadIdx.x] = s; __syncthreads();
    for (int o = 128; o; o >>= 1) { if (threadIdx.x < o) sh[threadIdx.x] += sh[threadIdx.x + o]; __syncthreads(); }
    float mu = sh[0] * (1.0f / DD); __syncthreads();
    float v = 0.f;
    for (int j = threadIdx.x; j < DD; j += 256) { float d = x[j] - mu; v += d * d; }
    sh[threadIdx.x] = v; __syncthreads();
    for (int o = 128; o; o >>= 1) { if (threadIdx.x < o) sh[threadIdx.x] += sh[threadIdx.x + o]; __syncthreads(); }
    float rstd = rsqrtf(sh[0] * (1.0f / DD) + 1e-5f);
    for (int j = threadIdx.x; j < DD; j += 256)
        g_xn[b * DD + j] = (x[j] - mu) * rstd * lnw[j];
}

// ---------------- lm_head (tied wte) + broadcast across T --------------------
// Each block: 128 vocab columns. Phase A: row_logits[4][128]. Phase B: write
// those values to all B*T output rows (output rows are identical per batch).
__global__ void k_lmhead(const float* __restrict__ wte, float* __restrict__ out) {
    __shared__ float sxn[BB * DD];
    __shared__ float rl[BB][128];
    for (int i = threadIdx.x; i < BB * DD; i += 256) sxn[i] = g_xn[i];
    __syncthreads();

    int v0 = blockIdx.x * 128;
    int warp = threadIdx.x >> 5, lane = threadIdx.x & 31;

    for (int vi = warp; vi < 128; vi += 8) {
        int v = v0 + vi;
        float a0 = 0.f, a1 = 0.f, a2 = 0.f, a3 = 0.f;
        if (v < VV) {
            const float* wr = wte + (size_t)v * DD;
            for (int j = lane; j < DD; j += 32) {
                float w = wr[j];
                a0 += w * sxn[j];
                a1 += w * sxn[DD + j];
                a2 += w * sxn[2 * DD + j];
                a3 += w * sxn[3 * DD + j];
            }
        }
        a0 = warp_sum(a0); a1 = warp_sum(a1); a2 = warp_sum(a2); a3 = warp_sum(a3);
        if (lane == 0) { rl[0][vi] = a0; rl[1][vi] = a1; rl[2][vi] = a2; rl[3][vi] = a3; }
    }
    __syncthreads();

    // broadcast: warp -> (batch b, half of T); lane owns 4 consecutive v's
    int b = warp >> 1;
    int half = warp & 1;
    int vb = lane * 4;
    float r0 = rl[b][vb], r1 = rl[b][vb + 1], r2 = rl[b][vb + 2], r3 = rl[b][vb + 3];
    bool g0 = (v0 + vb) < VV, g1 = (v0 + vb + 1) < VV,
         g2 = (v0 + vb + 2) < VV, g3 = (v0 + vb + 3) < VV;
    size_t base = ((size_t)(b * TT) + (size_t)half * 512) * VV + v0 + vb;
    #pragma unroll 4
    for (int t = 0; t < 512; t++) {
        float* o = out + base + (size_t)t * VV;
        if (g0) o[0] = r0;
        if (g1) o[1] = r1;
        if (g2) o[2] = r2;
        if (g3) o[3] = r3;
    }
}

// ---------------- launch ------------------------------------------------------
extern "C" void kernel_launch(void* const* d_in, const int* in_sizes, int n_in,
                              void* d_out, int out_size) {
    const int*   idx = (const int*)  d_in[0];
    const float* wte = (const float*)d_in[1];
    const float* wpe = (const float*)d_in[2];
    const float* lnw = (const float*)d_in[3];
    // d_in[4]=qw, d_in[5]=qb : dead (scores independent of Q)
    const float* kw  = (const float*)d_in[6];
    const float* kb  = (const float*)d_in[7];
    const float* vw  = (const float*)d_in[8];
    const float* vb  = (const float*)d_in[9];
    const float* fcw = (const float*)d_in[10];
    const float* pw  = (const float*)d_in[11];
    float* out = (float*)d_out;

    float *p_x, *p_ctx, *p_h;
    cudaGetSymbolAddress((void**)&p_x,   g_x);
    cudaGetSymbolAddress((void**)&p_ctx, g_ctx);
    cudaGetSymbolAddress((void**)&p_h,   g_h);

    // layer-1 attention reduced form
    k_prep<<<25, 256>>>(kw, kb);                 // kwm, kbm (layer 0 slices)
    k_kmean<<<512, 256>>>(idx, wte, wpe);
    k_softmax<<<BB, TT>>>();
    k_xbar<<<64, DD>>>(idx, wte, wpe);
    k_xbar_reduce<<<BB, DD>>>();                 // g_x = xbar

    // 4 layers: ctx = x@vw+vb ; h = gelu(ctx@fcw) ; x = h@pw
    for (int l = 0; l < LL; l++) {
        const float* vwl  = vw  + (size_t)l * DD * DD;
        const float* vbl  = vb  + (size_t)l * DD;
        const float* fcwl = fcw + (size_t)l * DD * DFF;
        const float* pwl  = pw  + (size_t)l * DFF * DD;

        k_gemm4<<<dim3(6, 8),  128>>>(p_x,   vwl,  DD,  DD,   96);
        k_finish<<<dim3(3, BB), 256>>>(p_ctx, vbl,  DD,  8,  0);

        k_gemm4<<<dim3(24, 6), 128>>>(p_ctx, fcwl, DD,  DFF, 128);
        k_finish<<<dim3(12, BB), 256>>>(p_h,  nullptr, DFF, 6, 1);

        k_gemm4<<<dim3(6, 16), 128>>>(p_h,   pwl,  DFF, DD,  192);
        k_finish<<<dim3(3, BB), 256>>>(p_x,  nullptr, DD, 16, 0);
    }

    k_lnf<<<BB, 256>>>(lnw);
    k_lmhead<<<(VV + 127) / 128, 256>>>(wte, out);
}

// round 2
// speedup vs baseline: 2.7695x; 2.7695x over previous
#include <cuda_runtime.h>
#include <cstdint>

#define BB 4
#define TT 1024
#define DD 768
#define LL 4
#define DFF 3072
#define VV 50257
#define NB 148
#define NT 512
#define NWARP (NB * (NT / 32))   // 2368 warps

// ---------------- scratch (static __device__, no allocations) ----------------
__device__ float g_kwm[DD];
__device__ float g_kbm;
__device__ float g_kmean[BB * TT];
__device__ float g_w[BB * TT];
__device__ float g_xpart[BB * 32 * DD];
__device__ float g_x[BB * DD];
__device__ float g_ctx[BB * DD];
__device__ float g_h[BB * DFF];
__device__ float g_part[294912];        // max(96*4*768, 24*4*3072) = 294912
__device__ float g_xn[BB * DD];
__device__ float g_logits[BB * VV];

__device__ unsigned g_arrive;           // zero-init; reset each barrier
__device__ unsigned g_phase;            // monotonically increasing generation

__device__ __forceinline__ float warp_sum(float v) {
    #pragma unroll
    for (int o = 16; o; o >>= 1) v += __shfl_xor_sync(0xffffffffu, v, o);
    return v;
}

// grid-wide barrier: all NB blocks co-resident (148 blocks, 1/SM guaranteed).
// __threadfence (gpu scope) emits CCTL.IVALL on sm_103a -> L1D invalidated,
// so post-barrier global reads observe other blocks' writes.
__device__ __forceinline__ void gsync() {
    __syncthreads();
    if (threadIdx.x == 0) {
        volatile unsigned* ph = &g_phase;
        unsigned gen = *ph;
        __threadfence();
        if (atomicAdd(&g_arrive, 1u) == NB - 1) {
            g_arrive = 0;
            __threadfence();
            *ph = gen + 1;
        } else {
            while (*ph == gen) { }
        }
        __threadfence();
    }
    __syncthreads();
}

// ---- skinny GEMM stage: 144 blocks, each block = (n-chunk of 256) x (2 k-chunks)
// part[(kch*4+b)*N + n] = sum over k-chunk of A[b,k]*W[k,n]
__device__ __forceinline__ void gemm_stage(const float* __restrict__ A,
                                           const float* __restrict__ W,
                                           int K, int N, int NC, int KC,
                                           float* sA) {
    int blk = blockIdx.x, tid = threadIdx.x;
    int nblocks = NC * ((K / KC) / 2);
    if (blk < nblocks) {
        int nc = blk % NC;
        int kpair = blk / NC;
        for (int i = tid; i < 2 * 4 * KC; i += NT) {
            int sub = i / (4 * KC);
            int rem = i - sub * 4 * KC;
            int b = rem / KC, kk = rem - b * KC;
            sA[(sub * 4 + b) * KC + kk] = A[b * K + (kpair * 2 + sub) * KC + kk];
        }
        __syncthreads();
        int sub = tid >> 8;
        int n = nc * 256 + (tid & 255);
        int kch = kpair * 2 + sub;
        const float* Wp = W + (size_t)(kch * KC) * N + n;
        const float* a = sA + sub * 4 * KC;
        float a0 = 0.f, a1 = 0.f, a2 = 0.f, a3 = 0.f;
        #pragma unroll 8
        for (int kk = 0; kk < KC; kk++) {
            float w = Wp[(size_t)kk * N];
            a0 += a[kk] * w;
            a1 += a[KC + kk] * w;
            a2 += a[2 * KC + kk] * w;
            a3 += a[3 * KC + kk] * w;
        }
        size_t base = (size_t)kch * BB * N + n;
        g_part[base]          = a0;
        g_part[base + N]      = a1;
        g_part[base + 2 * N]  = a2;
        g_part[base + 3 * N]  = a3;
        __syncthreads();
    }
}

__device__ __forceinline__ void reduce_stage(float* __restrict__ out,
                                             const float* __restrict__ bias,
                                             int N, int KCH, int act) {
    for (int t = blockIdx.x * NT + threadIdx.x; t < BB * N; t += NB * NT) {
        int b = t / N, n = t - b * N;
        float s = 0.f;
        #pragma unroll 8
        for (int kc = 0; kc < KCH; kc++)
            s += g_part[((size_t)kc * BB + b) * N + n];
        if (bias) s += bias[n];
        if (act) s = 0.5f * s * (1.0f + erff(s * 0.70710678118654752f));
        out[t] = s;
    }
}

// =================== the persistent kernel: everything but broadcast =========
__global__ __launch_bounds__(NT, 1)
void k_main(const int* __restrict__ idx, const float* __restrict__ wte,
            const float* __restrict__ wpe, const float* __restrict__ lnw,
            const float* __restrict__ kw,  const float* __restrict__ kb,
            const float* __restrict__ vw,  const float* __restrict__ vb,
            const float* __restrict__ fcw, const float* __restrict__ pw) {
    __shared__ float sm[BB * DD];   // 12 KB, reused per stage
    __shared__ int   smi[32];
    int blk = blockIdx.x, tid = threadIdx.x;
    int lane = tid & 31, wid = tid >> 5;
    int gw = blk * (NT / 32) + wid;

    // S0: kwm[i] = mean_d kw0[i,d]; kbm = mean(kb0)
    for (int i = gw; i < DD; i += NWARP) {
        const float* row = kw + (size_t)i * DD;
        float s = 0.f;
        #pragma unroll
        for (int jj = 0; jj < DD / 32; jj++) s += row[lane + jj * 32];
        s = warp_sum(s);
        if (lane == 0) g_kwm[i] = s * (1.0f / DD);
    }
    if (gw == NWARP - 1) {
        float s = 0.f;
        #pragma unroll
        for (int jj = 0; jj < DD / 32; jj++) s += kb[lane + jj * 32];
        s = warp_sum(s);
        if (lane == 0) g_kbm = s * (1.0f / DD);
    }
    gsync();

    // S1: k_mean[b,t] = (wte[idx]+wpe[t]) . kwm + kbm   (warp per token)
    for (int i = tid; i < DD; i += NT) sm[i] = g_kwm[i];
    __syncthreads();
    for (int tok = gw; tok < BB * TT; tok += NWARP) {
        int t = tok & (TT - 1);
        const float* e = wte + (size_t)idx[tok] * DD;
        const float* p = wpe + (size_t)t * DD;
        float s = 0.f;
        #pragma unroll
        for (int jj = 0; jj < DD / 32; jj++) {
            int j = lane + jj * 32;
            s += (e[j] + p[j]) * sm[j];
        }
        s = warp_sum(s);
        if (lane == 0) g_kmean[tok] = s + g_kbm;
    }
    gsync();

    // S2: softmax over T of cos(k_mean), per batch (blocks 0..3)
    if (blk < BB) {
        float v0 = cosf(g_kmean[blk * TT + tid]);
        float v1 = cosf(g_kmean[blk * TT + tid + 512]);
        sm[tid] = fmaxf(v0, v1); __syncthreads();
        for (int o = 256; o; o >>= 1) { if (tid < o) sm[tid] = fmaxf(sm[tid], sm[tid + o]); __syncthreads(); }
        float mx = sm[0]; __syncthreads();
        float e0 = expf(v0 - mx), e1 = expf(v1 - mx);
        sm[tid] = e0 + e1; __syncthreads();
        for (int o = 256; o; o >>= 1) { if (tid < o) sm[tid] += sm[tid + o]; __syncthreads(); }
        float inv = 1.0f / sm[0];
        g_w[blk * TT + tid]       = e0 * inv;
        g_w[blk * TT + tid + 512] = e1 * inv;
    }
    gsync();

    // S3: xbar partials (blocks 0..127: b = blk>>5, 32-token chunk c = blk&31)
    if (blk < 128) {
        int b = blk >> 5, c = blk & 31;
        if (tid < 32) {
            int t = c * 32 + tid;
            sm[tid]  = g_w[b * TT + t];
            smi[tid] = idx[b * TT + t];
        }
        __syncthreads();
        for (int d = tid; d < DD; d += NT) {
            float acc = 0.f;
            #pragma unroll 8
            for (int j = 0; j < 32; j++) {
                int t = c * 32 + j;
                acc += sm[j] * (wte[(size_t)smi[j] * DD + d] + wpe[(size_t)t * DD + d]);
            }
            g_xpart[(size_t)blk * DD + d] = acc;
        }
    }
    gsync();

    // S4: g_x[b,d] = sum_c xpart
    for (int t = blk * NT + tid; t < BB * DD; t += NB * NT) {
        int b = t / DD, d = t - b * DD;
        float s = 0.f;
        #pragma unroll
        for (int c = 0; c < 32; c++) s += g_xpart[(size_t)(b * 32 + c) * DD + d];
        g_x[t] = s;
    }
    gsync();

    // 4 layers: ctx = x@vw+vb ; h = gelu(ctx@fcw) ; x = h@pw
    for (int l = 0; l < LL; l++) {
        const float* vwl  = vw  + (size_t)l * DD * DD;
        const float* vbl  = vb  + (size_t)l * DD;
        const float* fcwl = fcw + (size_t)l * DD * DFF;
        const float* pwl  = pw  + (size_t)l * DFF * DD;

        gemm_stage(g_x,   vwl,  DD,  DD,  3, 8,  sm);  gsync();
        reduce_stage(g_ctx, vbl,     DD,  96, 0);      gsync();
        gemm_stage(g_ctx, fcwl, DD,  DFF, 12, 32, sm); gsync();
        reduce_stage(g_h,  nullptr, DFF, 24, 1);       gsync();
        gemm_stage(g_h,   pwl,  DFF, DD,  3, 32, sm);  gsync();
        reduce_stage(g_x,  nullptr,  DD,  96, 0);      gsync();
    }

    // ln_f on (B,D) state (blocks 0..3)
    if (blk < BB) {
        const float* x = g_x + blk * DD;
        float v0 = x[tid];
        float v1 = (tid + 512 < DD) ? x[tid + 512] : 0.f;
        sm[tid] = v0 + v1; __syncthreads();
        for (int o = 256; o; o >>= 1) { if (tid < o) sm[tid] += sm[tid + o]; __syncthreads(); }
        float mu = sm[0] * (1.0f / DD); __syncthreads();
        float d0 = v0 - mu, d1 = (tid + 512 < DD) ? (v1 - mu) : 0.f;
        sm[tid] = d0 * d0 + d1 * d1; __syncthreads();
        for (int o = 256; o; o >>= 1) { if (tid < o) sm[tid] += sm[tid + o]; __syncthreads(); }
        float rstd = rsqrtf(sm[0] * (1.0f / DD) + 1e-5f);
        g_xn[blk * DD + tid] = d0 * rstd * lnw[tid];
        if (tid + 512 < DD) g_xn[blk * DD + tid + 512] = d1 * rstd * lnw[tid + 512];
    }
    gsync();

    // logits: row_logits[b,v] = xn[b,:] . wte[v,:]   (warp per vocab row)
    for (int i = tid; i < BB * DD; i += NT) sm[i] = g_xn[i];
    __syncthreads();
    for (int v = gw; v < VV; v += NWARP) {
        const float* wr = wte + (size_t)v * DD;
        float a0 = 0.f, a1 = 0.f, a2 = 0.f, a3 = 0.f;
        #pragma unroll
        for (int jj = 0; jj < DD / 32; jj++) {
            int j = lane + jj * 32;
            float w = wr[j];
            a0 += w * sm[j];
            a1 += w * sm[DD + j];
            a2 += w * sm[2 * DD + j];
            a3 += w * sm[3 * DD + j];
        }
        a0 = warp_sum(a0); a1 = warp_sum(a1); a2 = warp_sum(a2); a3 = warp_sum(a3);
        if (lane == 0) {
            g_logits[v]          = a0;
            g_logits[VV + v]     = a1;
            g_logits[2 * VV + v] = a2;
            g_logits[3 * VV + v] = a3;
        }
    }
}

// =================== broadcast: out[b,t,:] = row_logits[b,:] =================
// One block per output row; float4 streaming stores with alignment-phase
// handling (VV % 4 == 1 shifts alignment by 1 float per row).
__global__ __launch_bounds__(256)
void k_bcast(float* __restrict__ out) {
    int r = blockIdx.x;                 // 0..4095
    int b = r >> 10;
    const float* src = g_logits + (size_t)b * VV;
    float* dst = out + (size_t)r * VV;
    int tid = threadIdx.x;

    int phase = (4 - (r & 3)) & 3;      // (r*VV) % 4 == r % 4
    if (tid < phase) dst[tid] = __ldg(src + tid);
    int nvec = (VV - phase) >> 2;
    float4* d4 = reinterpret_cast<float4*>(dst + phase);
    const float* s = src + phase;
    for (int i = tid; i < nvec; i += 256) {
        int k = 4 * i;
        float4 v;
        v.x = __ldg(s + k);
        v.y = __ldg(s + k + 1);
        v.z = __ldg(s + k + 2);
        v.w = __ldg(s + k + 3);
        __stcs(d4 + i, v);
    }
    int done = phase + 4 * nvec;
    int rem = VV - done;
    if (tid < rem) dst[done + tid] = __ldg(src + done + tid);
}

// ---------------- launch ------------------------------------------------------
extern "C" void kernel_launch(void* const* d_in, const int* in_sizes, int n_in,
                              void* d_out, int out_size) {
    const int*   idx = (const int*)  d_in[0];
    const float* wte = (const float*)d_in[1];
    const float* wpe = (const float*)d_in[2];
    const float* lnw = (const float*)d_in[3];
    // d_in[4]=qw, d_in[5]=qb : dead (scores independent of Q)
    const float* kw  = (const float*)d_in[6];
    const float* kb  = (const float*)d_in[7];
    const float* vw  = (const float*)d_in[8];
    const float* vb  = (const float*)d_in[9];
    const float* fcw = (const float*)d_in[10];
    const float* pw  = (const float*)d_in[11];
    float* out = (float*)d_out;

    k_main<<<NB, NT>>>(idx, wte, wpe, lnw, kw, kb, vw, vb, fcw, pw);
    k_bcast<<<BB * TT, 256>>>(out);
}